// round 4
// baseline (speedup 1.0000x reference)
#include <cuda_runtime.h>

#define FULL 0xFFFFFFFFu

constexpr int B = 2048;
constexpr int T = 4096;
constexpr int H = 8;

__device__ __forceinline__ float ex2f(float x) {
    float y; asm("ex2.approx.f32 %0, %1;" : "=f"(y) : "f"(x)); return y;
}
__device__ __forceinline__ float rcpf(float x) {
    float y; asm("rcp.approx.f32 %0, %1;" : "=f"(y) : "f"(x)); return y;
}

// Warp-per-batch 2-layer fused LSTM + linear head.
// Lane g owns gate row g (rows 0-7 = i, 8-15 = f, 16-23 = g, 24-31 = o).
__global__ void __launch_bounds__(64)
lstm2_kernel(const float* __restrict__ x,
             const float* __restrict__ Wih0, const float* __restrict__ Whh0,
             const float* __restrict__ bih0, const float* __restrict__ bhh0,
             const float* __restrict__ Wih1, const float* __restrict__ Whh1,
             const float* __restrict__ bih1, const float* __restrict__ bhh1,
             const float* __restrict__ Wlin, const float* __restrict__ blin,
             float* __restrict__ out)
{
    const int lane = threadIdx.x & 31;
    const int warp = (blockIdx.x * blockDim.x + threadIdx.x) >> 5;
    if (warp >= B) return;
    const int g = lane;
    const int unit = lane & 7;

    // ---- weights into registers (per-lane gate row) ----
    const float wih0  = Wih0[g];                 // [32,1]
    const float bias0 = bih0[g] + bhh0[g];
    const float bias1 = bih1[g] + bhh1[g];
    float whh0[H], wih1[H], whh1[H], wlin[H];
#pragma unroll
    for (int k = 0; k < H; k++) {
        whh0[k] = Whh0[g * H + k];
        wih1[k] = Wih1[g * H + k];
        whh1[k] = Whh1[g * H + k];
        wlin[k] = Wlin[k];
    }
    const float blinv = blin[0];

    // Branchless per-lane activation: a = as * rcp(1 + ex2(am * z)) + ab
    // sigmoid: am = -log2(e), as = 1, ab = 0
    // tanh   : am = -2*log2(e), as = 2, ab = -1   (lanes 16..23, the 'g' gate)
    const bool  isg = (lane >= 16) && (lane < 24);
    const float am  = isg ? -2.88539008177792681f : -1.44269504088896340f;
    const float as  = isg ?  2.0f : 1.0f;
    const float ab  = isg ? -1.0f : 0.0f;
    const float TM  = -2.88539008177792681f;     // for tanh(c)

    const float* xb = x   + (size_t)warp * T;
    float*       ob = out + (size_t)warp * T;

    float h1a[H], h2a[H];
#pragma unroll
    for (int k = 0; k < H; k++) { h1a[k] = 0.0f; h2a[k] = 0.0f; }
    float c1 = 0.0f, c2 = 0.0f;
    float predbuf = 0.0f;

    float xbuf = xb[lane];                       // chunk 0 prefetch
    for (int t0 = 0; t0 < T; t0 += 32) {
        // prefetch next chunk of x (coalesced, 128B per warp)
        float xnext = 0.0f;
        if (t0 + 32 < T) xnext = xb[t0 + 32 + lane];

#pragma unroll 8
        for (int tt = 0; tt < 32; tt++) {
            const float xt = __shfl_sync(FULL, xbuf, tt);

            // ---------------- layer 0 ----------------
            float acc = fmaf(wih0, xt, bias0);
#pragma unroll
            for (int k = 0; k < H; k++) acc = fmaf(whh0[k], h1a[k], acc);
            const float a0 = fmaf(as, rcpf(1.0f + ex2f(am * acc)), ab);

            // gather f,g,o for this lane's unit (lanes<8 hold valid i == a0)
            const float f0 = __shfl_sync(FULL, a0, unit + 8);
            const float g0 = __shfl_sync(FULL, a0, unit + 16);
            const float o0 = __shfl_sync(FULL, a0, unit + 24);
            c1 = fmaf(f0, c1, a0 * g0);          // valid in lanes<8
            const float th1 = fmaf(2.0f, rcpf(1.0f + ex2f(TM * c1)), -1.0f);
            const float h1  = o0 * th1;
            // distribute new h1 (lane k holds h1[k] for k<8)
#pragma unroll
            for (int k = 0; k < H; k++) h1a[k] = __shfl_sync(FULL, h1, k);

            // ---------------- layer 1 ----------------
            float acc2 = bias1;
#pragma unroll
            for (int k = 0; k < H; k++) acc2 = fmaf(wih1[k], h1a[k], acc2);
#pragma unroll
            for (int k = 0; k < H; k++) acc2 = fmaf(whh1[k], h2a[k], acc2);
            const float a1 = fmaf(as, rcpf(1.0f + ex2f(am * acc2)), ab);

            const float f1 = __shfl_sync(FULL, a1, unit + 8);
            const float g1 = __shfl_sync(FULL, a1, unit + 16);
            const float o1 = __shfl_sync(FULL, a1, unit + 24);
            c2 = fmaf(f1, c2, a1 * g1);
            const float th2 = fmaf(2.0f, rcpf(1.0f + ex2f(TM * c2)), -1.0f);
            const float h2  = o1 * th2;
#pragma unroll
            for (int k = 0; k < H; k++) h2a[k] = __shfl_sync(FULL, h2, k);

            // ---------------- output head ----------------
            float p = blinv;
#pragma unroll
            for (int k = 0; k < H; k++) p = fmaf(wlin[k], h2a[k], p);
            if (lane == tt) predbuf = p;         // lane tt banks step t0+tt
        }

        ob[t0 + lane] = predbuf;                 // coalesced 128B store
        xbuf = xnext;
    }
}

extern "C" void kernel_launch(void* const* d_in, const int* in_sizes, int n_in,
                              void* d_out, int out_size)
{
    const float* x    = (const float*)d_in[0];
    const float* Wih0 = (const float*)d_in[1];
    const float* Whh0 = (const float*)d_in[2];
    const float* bih0 = (const float*)d_in[3];
    const float* bhh0 = (const float*)d_in[4];
    const float* Wih1 = (const float*)d_in[5];
    const float* Whh1 = (const float*)d_in[6];
    const float* bih1 = (const float*)d_in[7];
    const float* bhh1 = (const float*)d_in[8];
    const float* Wlin = (const float*)d_in[9];
    const float* blin = (const float*)d_in[10];
    float* out = (float*)d_out;

    // 2048 warps = one per batch element; 64-thread blocks for wave balance
    const int threads = 64;
    const int blocks  = (B * 32) / threads;      // 1024
    lstm2_kernel<<<blocks, threads>>>(x, Wih0, Whh0, bih0, bhh0,
                                      Wih1, Whh1, bih1, bhh1, Wlin, blin, out);
}

// round 5
// speedup vs baseline: 1.5339x; 1.5339x over previous
#include <cuda_runtime.h>

#define FULL 0xFFFFFFFFu
typedef unsigned long long u64;

constexpr int B = 2048;
constexpr int T = 4096;

__device__ __forceinline__ float ex2f(float x){ float y; asm("ex2.approx.f32 %0,%1;":"=f"(y):"f"(x)); return y; }
__device__ __forceinline__ float rcpf(float x){ float y; asm("rcp.approx.f32 %0,%1;":"=f"(y):"f"(x)); return y; }
// sm_103a packed f32x2 ops (ptxas never auto-fuses these from C++)
__device__ __forceinline__ u64 ffma2(u64 a, u64 b, u64 c){
    u64 d; asm("fma.rn.f32x2 %0,%1,%2,%3;" : "=l"(d) : "l"(a), "l"(b), "l"(c)); return d;
}
__device__ __forceinline__ u64 fadd2(u64 a, u64 b){
    u64 d; asm("add.rn.f32x2 %0,%1,%2;" : "=l"(d) : "l"(a), "l"(b)); return d;
}
__device__ __forceinline__ u64 pack2(float lo, float hi){
    u64 d; asm("mov.b64 %0,{%1,%2};" : "=l"(d) : "f"(lo), "f"(hi)); return d;
}
__device__ __forceinline__ void unpack2(u64 v, float& lo, float& hi){
    asm("mov.b64 {%0,%1},%2;" : "=f"(lo), "=f"(hi) : "l"(v));
}
__device__ __forceinline__ u64 dup2(float v){ return pack2(v, v); }
// arg is pre-scaled by -log2e (sigmoid) or -2log2e (tanh form): sig = rcp(1 + 2^z)
__device__ __forceinline__ float siglike(float z){ return rcpf(1.0f + ex2f(z)); }

// 4 batches per warp; lane = (batch b_local = lane>>3, unit u = lane&7).
// Each lane computes all 4 gates (i,f,g,o) of its unit, pair-packed as
// (i,f) and (g,o) in f32x2. Layers software-pipelined: L1[t] and L0[t+1]
// both depend only on h1[t] -> two independent chains per loop body.
__global__ void __launch_bounds__(64, 1)
lstm2_kernel(const float* __restrict__ x,
             const float* __restrict__ Wih0, const float* __restrict__ Whh0,
             const float* __restrict__ bih0, const float* __restrict__ bhh0,
             const float* __restrict__ Wih1, const float* __restrict__ Whh1,
             const float* __restrict__ bih1, const float* __restrict__ bhh1,
             const float* __restrict__ Wlin, const float* __restrict__ blin,
             float* __restrict__ out)
{
    const int lane = threadIdx.x & 31;
    const int warp = (blockIdx.x * blockDim.x + threadIdx.x) >> 5;
    const int u    = lane & 7;
    const int base = lane & 24;                  // first lane of this batch group
    const int b    = warp * 4 + (lane >> 3);     // my batch element

    const float Ss = -1.44269504088896340f;      // -log2(e)   : sigmoid gates
    const float Sg = -2.88539008177792681f;      // -2*log2(e) : tanh gate
    const float TM = -2.88539008177792681f;      // tanh(c) arg scale

    // ---- weights: pre-scaled by activation constant, pair-packed ----
    u64 whh0_if[8], whh0_go[8], wih1_if[8], wih1_go[8], whh1_if[8], whh1_go[8];
#pragma unroll
    for (int k = 0; k < 8; k++) {
        whh0_if[k] = pack2(Ss*Whh0[u*8+k],        Ss*Whh0[(8+u)*8+k]);
        whh0_go[k] = pack2(Sg*Whh0[(16+u)*8+k],   Ss*Whh0[(24+u)*8+k]);
        wih1_if[k] = pack2(Ss*Wih1[u*8+k],        Ss*Wih1[(8+u)*8+k]);
        wih1_go[k] = pack2(Sg*Wih1[(16+u)*8+k],   Ss*Wih1[(24+u)*8+k]);
        whh1_if[k] = pack2(Ss*Whh1[u*8+k],        Ss*Whh1[(8+u)*8+k]);
        whh1_go[k] = pack2(Sg*Whh1[(16+u)*8+k],   Ss*Whh1[(24+u)*8+k]);
    }
    const u64 wx_if0 = pack2(Ss*Wih0[u],      Ss*Wih0[8+u]);
    const u64 wx_go0 = pack2(Sg*Wih0[16+u],   Ss*Wih0[24+u]);
    const u64 b_if0  = pack2(Ss*(bih0[u]+bhh0[u]),       Ss*(bih0[8+u]+bhh0[8+u]));
    const u64 b_go0  = pack2(Sg*(bih0[16+u]+bhh0[16+u]), Ss*(bih0[24+u]+bhh0[24+u]));
    const u64 b_if1  = pack2(Ss*(bih1[u]+bhh1[u]),       Ss*(bih1[8+u]+bhh1[8+u]));
    const u64 b_go1  = pack2(Sg*(bih1[16+u]+bhh1[16+u]), Ss*(bih1[24+u]+bhh1[24+u]));
    float wl[8];
#pragma unroll
    for (int k = 0; k < 8; k++) wl[k] = Wlin[k];
    const float blv = blin[0];

    // ---- state: h vectors kept dup-packed (v,v) for f32x2 matvecs ----
    u64 h1x[8], h2x[8];
#pragma unroll
    for (int k = 0; k < 8; k++) { h1x[k] = 0ull; h2x[k] = 0ull; }
    float c1 = 0.f, c2 = 0.f, pbuf = 0.f;

    const float4* xb4 = reinterpret_cast<const float4*>(x + (size_t)b * T);
    float*        ob  = out + (size_t)b * T;

    auto L0 = [&](float xt) {
        u64 xd  = dup2(xt);
        u64 aif = ffma2(wx_if0, xd, b_if0);
        u64 ago = ffma2(wx_go0, xd, b_go0);
#pragma unroll
        for (int k = 0; k < 8; k++) {
            aif = ffma2(whh0_if[k], h1x[k], aif);
            ago = ffma2(whh0_go[k], h1x[k], ago);
        }
        float zi, zf, zg, zo;
        unpack2(aif, zi, zf);
        unpack2(ago, zg, zo);
        float iv = siglike(zi), fv = siglike(zf);
        float gv = fmaf(2.f, siglike(zg), -1.f);
        float ov = siglike(zo);
        c1 = fmaf(fv, c1, iv * gv);
        float th = fmaf(2.f, siglike(TM * c1), -1.f);
        float h  = ov * th;
#pragma unroll
        for (int k = 0; k < 8; k++)
            h1x[k] = dup2(__shfl_sync(FULL, h, base + k));
    };

    // prologue: compute h1[0] from x[0]
    float4 xv = xb4[u];                          // chunk 0: lane holds x[b][4u..4u+3]
    L0(__shfl_sync(FULL, xv.x, base));

    for (int t0 = 0; t0 < T; t0 += 32) {
        float4 xvn = make_float4(0.f, 0.f, 0.f, 0.f);
        if (t0 + 32 < T) xvn = xb4[(t0 + 32) / 4 + u];   // prefetch next chunk

#pragma unroll 1
        for (int sub = 0; sub < 8; sub++) {
#pragma unroll
            for (int q = 0; q < 4; q++) {
                // ======== layer 1 + head for out-step t = t0 + 4*sub + q ========
                // consumes h1x = h1[t] (produced by previous iteration's L0)
                u64 aif = b_if1, ago = b_go1, bif = 0ull, bgo = 0ull;
#pragma unroll
                for (int k = 0; k < 8; k++) {
                    aif = ffma2(wih1_if[k], h1x[k], aif);
                    ago = ffma2(wih1_go[k], h1x[k], ago);
                    bif = ffma2(whh1_if[k], h2x[k], bif);
                    bgo = ffma2(whh1_go[k], h2x[k], bgo);
                }
                aif = fadd2(aif, bif);
                ago = fadd2(ago, bgo);
                float zi, zf, zg, zo;
                unpack2(aif, zi, zf);
                unpack2(ago, zg, zo);
                float iv = siglike(zi), fv = siglike(zf);
                float gv = fmaf(2.f, siglike(zg), -1.f);
                float ov = siglike(zo);
                c2 = fmaf(fv, c2, iv * gv);
                float th = fmaf(2.f, siglike(TM * c2), -1.f);
                float h2 = ov * th;
                // distribute h2, compute head on the fly
                float p = blv;
#pragma unroll
                for (int k = 0; k < 8; k++) {
                    float hs = __shfl_sync(FULL, h2, base + k);
                    p = fmaf(wl[k], hs, p);
                    h2x[k] = dup2(hs);
                }
                if (((sub * 4 + q) & 7) == u) pbuf = p;   // bank out[t] in lane t&7

                // ======== layer 0 for x-step t+1 (independent chain) ========
                float xsrc; int srcl;
                if      (q == 0) { xsrc = xv.y; srcl = base + sub; }
                else if (q == 1) { xsrc = xv.z; srcl = base + sub; }
                else if (q == 2) { xsrc = xv.w; srcl = base + sub; }
                else             { xsrc = (sub == 7) ? xvn.x : xv.x;
                                   srcl = base + ((sub + 1) & 7); }
                L0(__shfl_sync(FULL, xsrc, srcl));
                // at the very last step this computes a harmless garbage h1[T]
                // from the zero-filled xvn (never read, no OOB access)
            }
            if (sub & 1)                          // 8 steps banked -> coalesced store
                ob[t0 + sub * 4 - 4 + u] = pbuf;
        }
        xv = xvn;
    }
}

extern "C" void kernel_launch(void* const* d_in, const int* in_sizes, int n_in,
                              void* d_out, int out_size)
{
    const float* x    = (const float*)d_in[0];
    const float* Wih0 = (const float*)d_in[1];
    const float* Whh0 = (const float*)d_in[2];
    const float* bih0 = (const float*)d_in[3];
    const float* bhh0 = (const float*)d_in[4];
    const float* Wih1 = (const float*)d_in[5];
    const float* Whh1 = (const float*)d_in[6];
    const float* bih1 = (const float*)d_in[7];
    const float* bhh1 = (const float*)d_in[8];
    const float* Wlin = (const float*)d_in[9];
    const float* blin = (const float*)d_in[10];
    float* out = (float*)d_out;

    // 512 warps (4 batches each), 64-thread blocks -> 256 blocks
    const int threads = 64;
    const int blocks  = (B / 4) * 32 / threads;   // 256
    lstm2_kernel<<<blocks, threads>>>(x, Wih0, Whh0, bih0, bhh0,
                                      Wih1, Whh1, bih1, bhh1, Wlin, blin, out);
}

// round 6
// speedup vs baseline: 2.3142x; 1.5087x over previous
#include <cuda_runtime.h>

#define FULL 0xFFFFFFFFu
typedef unsigned long long u64;

constexpr int B = 2048;
constexpr int T = 4096;

__device__ __forceinline__ float tanhf_a(float x){ float y; asm("tanh.approx.f32 %0,%1;":"=f"(y):"f"(x)); return y; }
// sm_103a packed f32x2 ops (ptxas never auto-fuses these from C++)
__device__ __forceinline__ u64 ffma2(u64 a, u64 b, u64 c){
    u64 d; asm("fma.rn.f32x2 %0,%1,%2,%3;" : "=l"(d) : "l"(a), "l"(b), "l"(c)); return d;
}
__device__ __forceinline__ u64 fadd2(u64 a, u64 b){
    u64 d; asm("add.rn.f32x2 %0,%1,%2;" : "=l"(d) : "l"(a), "l"(b)); return d;
}
__device__ __forceinline__ u64 pack2(float lo, float hi){
    u64 d; asm("mov.b64 %0,{%1,%2};" : "=l"(d) : "f"(lo), "f"(hi)); return d;
}
__device__ __forceinline__ void unpack2(u64 v, float& lo, float& hi){
    asm("mov.b64 {%0,%1},%2;" : "=f"(lo), "=f"(hi) : "l"(v));
}
__device__ __forceinline__ u64 dup2(float v){ return pack2(v, v); }

// 4 batches per warp; lane = (batch b_local = lane>>3, unit u = lane&7).
// Each lane computes all 4 gates (i,f,g,o) of its unit, pair-packed as
// (i,f) and (g,o) in f32x2. Layers software-pipelined: L1[t] and L0[t+1]
// both depend only on h1[t] -> two independent chains per loop body.
// Activations via MUFU.TANH: sigmoid(z) = 0.5*tanh(0.5 z) + 0.5, the 0.5
// pre-folded into the weights/biases of the sigmoid gates (i,f,o).
__global__ void __launch_bounds__(128, 1)
lstm2_kernel(const float* __restrict__ x,
             const float* __restrict__ Wih0, const float* __restrict__ Whh0,
             const float* __restrict__ bih0, const float* __restrict__ bhh0,
             const float* __restrict__ Wih1, const float* __restrict__ Whh1,
             const float* __restrict__ bih1, const float* __restrict__ bhh1,
             const float* __restrict__ Wlin, const float* __restrict__ blin,
             float* __restrict__ out)
{
    const int lane = threadIdx.x & 31;
    const int warp = (blockIdx.x * blockDim.x + threadIdx.x) >> 5;
    const int u    = lane & 7;
    const int base = lane & 24;                  // first lane of this batch group
    const int b    = warp * 4 + (lane >> 3);     // my batch element

    const float Hs = 0.5f;                       // sigmoid gates: pre-scale 1/2
    const float Gs = 1.0f;                       // tanh gate: direct

    // ---- weights: pre-scaled by activation constant, pair-packed ----
    u64 whh0_if[8], whh0_go[8], wih1_if[8], wih1_go[8], whh1_if[8], whh1_go[8];
#pragma unroll
    for (int k = 0; k < 8; k++) {
        whh0_if[k] = pack2(Hs*Whh0[u*8+k],        Hs*Whh0[(8+u)*8+k]);
        whh0_go[k] = pack2(Gs*Whh0[(16+u)*8+k],   Hs*Whh0[(24+u)*8+k]);
        wih1_if[k] = pack2(Hs*Wih1[u*8+k],        Hs*Wih1[(8+u)*8+k]);
        wih1_go[k] = pack2(Gs*Wih1[(16+u)*8+k],   Hs*Wih1[(24+u)*8+k]);
        whh1_if[k] = pack2(Hs*Whh1[u*8+k],        Hs*Whh1[(8+u)*8+k]);
        whh1_go[k] = pack2(Gs*Whh1[(16+u)*8+k],   Hs*Whh1[(24+u)*8+k]);
    }
    const u64 wx_if0 = pack2(Hs*Wih0[u],      Hs*Wih0[8+u]);
    const u64 wx_go0 = pack2(Gs*Wih0[16+u],   Hs*Wih0[24+u]);
    const u64 b_if0  = pack2(Hs*(bih0[u]+bhh0[u]),       Hs*(bih0[8+u]+bhh0[8+u]));
    const u64 b_go0  = pack2(Gs*(bih0[16+u]+bhh0[16+u]), Hs*(bih0[24+u]+bhh0[24+u]));
    const u64 b_if1  = pack2(Hs*(bih1[u]+bhh1[u]),       Hs*(bih1[8+u]+bhh1[8+u]));
    const u64 b_go1  = pack2(Gs*(bih1[16+u]+bhh1[16+u]), Hs*(bih1[24+u]+bhh1[24+u]));
    float wl[8];
#pragma unroll
    for (int k = 0; k < 8; k++) wl[k] = Wlin[k];
    const float blv = blin[0];

    // ---- state: h vectors kept dup-packed (v,v) for f32x2 matvecs ----
    u64 h1x[8], h2x[8];
#pragma unroll
    for (int k = 0; k < 8; k++) { h1x[k] = 0ull; h2x[k] = 0ull; }
    float c1 = 0.f, c2 = 0.f, pbuf = 0.f;

    const float4* xb4 = reinterpret_cast<const float4*>(x + (size_t)b * T);
    float*        ob  = out + (size_t)b * T;

    auto L0 = [&](float xt) {
        u64 xd  = dup2(xt);
        u64 aif = ffma2(wx_if0, xd, b_if0);
        u64 ago = ffma2(wx_go0, xd, b_go0);
#pragma unroll
        for (int k = 0; k < 8; k++) {
            aif = ffma2(whh0_if[k], h1x[k], aif);
            ago = ffma2(whh0_go[k], h1x[k], ago);
        }
        float zi, zf, zg, zo;
        unpack2(aif, zi, zf);
        unpack2(ago, zg, zo);
        float iv = fmaf(0.5f, tanhf_a(zi), 0.5f);
        float fv = fmaf(0.5f, tanhf_a(zf), 0.5f);
        float gv = tanhf_a(zg);
        float ov = fmaf(0.5f, tanhf_a(zo), 0.5f);
        c1 = fmaf(fv, c1, iv * gv);
        float h = ov * tanhf_a(c1);
#pragma unroll
        for (int k = 0; k < 8; k++)
            h1x[k] = dup2(__shfl_sync(FULL, h, base + k));
    };

    // prologue: compute h1[0] from x[0]
    float4 xv = xb4[u];                          // chunk 0: lane holds x[b][4u..4u+3]
    L0(__shfl_sync(FULL, xv.x, base));

    for (int t0 = 0; t0 < T; t0 += 32) {
        float4 xvn = make_float4(0.f, 0.f, 0.f, 0.f);
        if (t0 + 32 < T) xvn = xb4[(t0 + 32) / 4 + u];   // prefetch next chunk

#pragma unroll 1
        for (int sub = 0; sub < 8; sub++) {
#pragma unroll
            for (int q = 0; q < 4; q++) {
                // ======== layer 1 + head for out-step t = t0 + 4*sub + q ========
                // consumes h1x = h1[t] (produced by previous iteration's L0)
                u64 aif = b_if1, ago = b_go1, bif = 0ull, bgo = 0ull;
#pragma unroll
                for (int k = 0; k < 8; k++) {
                    aif = ffma2(wih1_if[k], h1x[k], aif);
                    ago = ffma2(wih1_go[k], h1x[k], ago);
                    bif = ffma2(whh1_if[k], h2x[k], bif);
                    bgo = ffma2(whh1_go[k], h2x[k], bgo);
                }
                aif = fadd2(aif, bif);
                ago = fadd2(ago, bgo);
                float zi, zf, zg, zo;
                unpack2(aif, zi, zf);
                unpack2(ago, zg, zo);
                float iv = fmaf(0.5f, tanhf_a(zi), 0.5f);
                float fv = fmaf(0.5f, tanhf_a(zf), 0.5f);
                float gv = tanhf_a(zg);
                float ov = fmaf(0.5f, tanhf_a(zo), 0.5f);
                c2 = fmaf(fv, c2, iv * gv);
                float h2 = ov * tanhf_a(c2);
                // distribute h2, compute head on the fly
                float p = blv;
#pragma unroll
                for (int k = 0; k < 8; k++) {
                    float hs = __shfl_sync(FULL, h2, base + k);
                    p = fmaf(wl[k], hs, p);
                    h2x[k] = dup2(hs);
                }
                if (((sub * 4 + q) & 7) == u) pbuf = p;   // bank out[t] in lane t&7

                // ======== layer 0 for x-step t+1 (independent chain) ========
                float xsrc; int srcl;
                if      (q == 0) { xsrc = xv.y; srcl = base + sub; }
                else if (q == 1) { xsrc = xv.z; srcl = base + sub; }
                else if (q == 2) { xsrc = xv.w; srcl = base + sub; }
                else             { xsrc = (sub == 7) ? xvn.x : xv.x;
                                   srcl = base + ((sub + 1) & 7); }
                L0(__shfl_sync(FULL, xsrc, srcl));
                // at the very last step this computes a harmless garbage h1[T]
                // from the zero-filled xvn (never read, no OOB access)
            }
            if (sub & 1)                          // 8 steps banked -> coalesced store
                ob[t0 + sub * 4 - 4 + u] = pbuf;
        }
        xv = xvn;
    }
}

extern "C" void kernel_launch(void* const* d_in, const int* in_sizes, int n_in,
                              void* d_out, int out_size)
{
    const float* x    = (const float*)d_in[0];
    const float* Wih0 = (const float*)d_in[1];
    const float* Whh0 = (const float*)d_in[2];
    const float* bih0 = (const float*)d_in[3];
    const float* bhh0 = (const float*)d_in[4];
    const float* Wih1 = (const float*)d_in[5];
    const float* Whh1 = (const float*)d_in[6];
    const float* bih1 = (const float*)d_in[7];
    const float* bhh1 = (const float*)d_in[8];
    const float* Wlin = (const float*)d_in[9];
    const float* blin = (const float*)d_in[10];
    float* out = (float*)d_out;

    // 512 warps (4 batches each); 128-thread blocks so the block's 4 warps
    // land on all 4 SMSPs (wid%4) -> 128 blocks, one warp per SMSP.
    const int threads = 128;
    const int blocks  = (B / 4) * 32 / threads;   // 128
    lstm2_kernel<<<blocks, threads>>>(x, Wih0, Whh0, bih0, bhh0,
                                      Wih1, Whh1, bih1, bhh1, Wlin, blin, out);
}